// round 1
// baseline (speedup 1.0000x reference)
#include <cuda_runtime.h>
#include <math.h>

// Problem constants (fixed by the reference).
#define NN 65536   // nodes
#define KK 8       // children
#define HH 128     // hidden size
#define TT 4       // types
#define NT 8       // nodes per block in main kernel
#define BLOCKS_PER_TYPE (NN / NT)   // 8192

// ---------------- device scratch (no allocations allowed) ----------------
__device__ int g_cnt[TT];
__device__ int g_base[TT + 1];
__device__ int g_cursor[TT];
__device__ int g_sorted[NN];

// ---------------- partition pipeline ----------------
__global__ void k_zero() {
    if (threadIdx.x < TT) g_cnt[threadIdx.x] = 0;
}

__global__ void k_hist(const int* __restrict__ type_id) {
    __shared__ int sc[TT];
    if (threadIdx.x < TT) sc[threadIdx.x] = 0;
    __syncthreads();
    int n = blockIdx.x * blockDim.x + threadIdx.x;
    atomicAdd(&sc[type_id[n]], 1);
    __syncthreads();
    if (threadIdx.x < TT) atomicAdd(&g_cnt[threadIdx.x], sc[threadIdx.x]);
}

__global__ void k_scan() {
    g_base[0] = 0;
    for (int t = 0; t < TT; t++) {
        g_base[t + 1] = g_base[t] + g_cnt[t];
        g_cursor[t] = g_base[t];
    }
}

// Warp-aggregated scatter: 4 global atomics per warp instead of 32.
__global__ void k_scatter(const int* __restrict__ type_id) {
    int n = blockIdx.x * blockDim.x + threadIdx.x;
    int t = type_id[n];
    int lane = threadIdx.x & 31;
#pragma unroll
    for (int tt = 0; tt < TT; tt++) {
        unsigned m = __ballot_sync(0xffffffffu, t == tt);
        if (t == tt) {
            int leader = __ffs(m) - 1;
            int base = 0;
            if (lane == leader) base = atomicAdd(&g_cursor[tt], __popc(m));
            base = __shfl_sync(m, base, leader);
            int rank = __popc(m & ((1u << lane) - 1));
            g_sorted[base + rank] = n;
        }
    }
}

// ---------------- main kernel ----------------
// Block = NT same-type nodes. 128 threads; thread o owns output column o.
// out[n, 0:384)  = h_sum @ U_iou[t] + b_iou[t]
// out[n, 384:512) = sum_k sigmoid(f_input[n] + h[n,k] @ U_f[t] + b_f[t]) * c[n,k]
__global__ __launch_bounds__(128) void k_main(
    const float* __restrict__ h, const float* __restrict__ c,
    const float* __restrict__ f_input,
    const float* __restrict__ U_iou, const float* __restrict__ b_iou,
    const float* __restrict__ U_f, const float* __restrict__ b_f,
    float* __restrict__ out)
{
    __shared__ __align__(16) float sh_h[NT][KK][HH];   // 32 KB
    __shared__ float sh_hs[NT][HH];                    // 4 KB
    __shared__ int sh_node[NT];

    const int t = blockIdx.x / BLOCKS_PER_TYPE;
    const int tb = blockIdx.x - t * BLOCKS_PER_TYPE;
    const int start = g_base[t] + tb * NT;
    const int end = g_base[t + 1];
    if (start >= end) return;
    const int cnt = min(NT, end - start);
    const int o = threadIdx.x;

    if (o < NT) sh_node[o] = (o < cnt) ? g_sorted[start + o] : 0;
    __syncthreads();

    // Gather h rows for the tile (float4, coalesced within each 4KB row).
    const int F4_PER_NODE = KK * HH / 4;  // 256
    for (int idx = o; idx < NT * F4_PER_NODE; idx += 128) {
        int ni = idx / F4_PER_NODE;
        int off = idx - ni * F4_PER_NODE;
        float4 v = make_float4(0.f, 0.f, 0.f, 0.f);
        if (ni < cnt)
            v = reinterpret_cast<const float4*>(h)[sh_node[ni] * F4_PER_NODE + off];
        reinterpret_cast<float4*>(&sh_h[0][0][0])[idx] = v;
    }
    __syncthreads();

    // Child-sum per node.
    for (int idx = o; idx < NT * HH; idx += 128) {
        int ni = idx >> 7, j = idx & 127;
        float s = 0.f;
#pragma unroll
        for (int k = 0; k < KK; k++) s += sh_h[ni][k][j];
        sh_hs[ni][j] = s;
    }
    __syncthreads();

    // ---- IOU: iou[n, o+{0,128,256}] = sum_j hs[n,j] * U_iou[t][j, o+{..}] ----
    const float* Ut = U_iou + t * (HH * 3 * HH);
    float a0[NT], a1[NT], a2[NT];
#pragma unroll
    for (int ni = 0; ni < NT; ni++) { a0[ni] = 0.f; a1[ni] = 0.f; a2[ni] = 0.f; }

#pragma unroll 4
    for (int j = 0; j < HH; j++) {
        float u0 = Ut[j * 384 + o];
        float u1 = Ut[j * 384 + 128 + o];
        float u2 = Ut[j * 384 + 256 + o];
#pragma unroll
        for (int ni = 0; ni < NT; ni++) {
            float s = sh_hs[ni][j];
            a0[ni] = fmaf(s, u0, a0[ni]);
            a1[ni] = fmaf(s, u1, a1[ni]);
            a2[ni] = fmaf(s, u2, a2[ni]);
        }
    }
    {
        float bi0 = b_iou[t * 384 + o];
        float bi1 = b_iou[t * 384 + 128 + o];
        float bi2 = b_iou[t * 384 + 256 + o];
        for (int ni = 0; ni < cnt; ni++) {
            int n = sh_node[ni];
            out[n * 512 + o]       = a0[ni] + bi0;
            out[n * 512 + 128 + o] = a1[ni] + bi1;
            out[n * 512 + 256 + o] = a2[ni] + bi2;
        }
    }

    // ---- Forget gates + cell aggregation ----
    const float* Uf = U_f + t * (HH * HH);
    const float bf = b_f[t * HH + o];

    for (int g = 0; g < NT; g += 4) {   // 2 passes of 4 nodes x 8 children = 32 accs
        float fa[4][KK];
#pragma unroll
        for (int ni = 0; ni < 4; ni++)
#pragma unroll
            for (int k = 0; k < KK; k++) fa[ni][k] = 0.f;

#pragma unroll 2
        for (int j4 = 0; j4 < HH / 4; j4++) {
            float u0 = Uf[(j4 * 4 + 0) * HH + o];
            float u1 = Uf[(j4 * 4 + 1) * HH + o];
            float u2 = Uf[(j4 * 4 + 2) * HH + o];
            float u3 = Uf[(j4 * 4 + 3) * HH + o];
#pragma unroll
            for (int ni = 0; ni < 4; ni++) {
#pragma unroll
                for (int k = 0; k < KK; k++) {
                    float4 hv = *reinterpret_cast<const float4*>(&sh_h[g + ni][k][j4 * 4]);
                    float f = fa[ni][k];
                    f = fmaf(hv.x, u0, f);
                    f = fmaf(hv.y, u1, f);
                    f = fmaf(hv.z, u2, f);
                    f = fmaf(hv.w, u3, f);
                    fa[ni][k] = f;
                }
            }
        }

#pragma unroll
        for (int ni = 0; ni < 4; ni++) {
            if (g + ni < cnt) {
                int n = sh_node[g + ni];
                float fi = f_input[n * HH + o] + bf;
                float ca = 0.f;
#pragma unroll
                for (int k = 0; k < KK; k++) {
                    float x = fa[ni][k] + fi;
                    float s = 1.f / (1.f + __expf(-x));
                    ca = fmaf(s, c[n * (KK * HH) + k * HH + o], ca);
                }
                out[n * 512 + 384 + o] = ca;
            }
        }
    }
}

// ---------------- launch ----------------
extern "C" void kernel_launch(void* const* d_in, const int* in_sizes, int n_in,
                              void* d_out, int out_size) {
    const float* h       = (const float*)d_in[0];
    const float* c       = (const float*)d_in[1];
    const float* f_input = (const float*)d_in[2];
    const int*   type_id = (const int*)d_in[3];
    const float* U_iou   = (const float*)d_in[4];
    const float* b_iou   = (const float*)d_in[5];
    const float* U_f     = (const float*)d_in[6];
    const float* b_f     = (const float*)d_in[7];
    float* out = (float*)d_out;

    k_zero<<<1, 32>>>();
    k_hist<<<NN / 256, 256>>>(type_id);
    k_scan<<<1, 1>>>();
    k_scatter<<<NN / 256, 256>>>(type_id);
    k_main<<<TT * BLOCKS_PER_TYPE, 128>>>(h, c, f_input, U_iou, b_iou, U_f, b_f, out);
}